// round 3
// baseline (speedup 1.0000x reference)
#include <cuda_runtime.h>
#include <cuda_bf16.h>
#include <cstdint>

// ---------------------------------------------------------------------------
// ResidualVQ restructured:
//   z_i^(l) = A_l(token) - sum_{j<l} M[l][j] @ zq_j + v_l
//   A = z_e @ Wd_all^T   (one GEMM, 32768x1024x128)
//   M[l][j] = Wd_l @ Wu_j (16x16),  v_l = bd_l - Wd_l @ sum_{j<l} bu_j
// Distances: score_k = ||cbn_k||^2 - 2 * zn . (cb_k * inv_k)   (argmin, fp32)
// ---------------------------------------------------------------------------

#define NTOK   32768
#define DIM    1024
#define KCODES 1024
#define CDIM   16
#define LLAY   8
#define LC     128           // L*CD
#define TOKB   64            // tokens per block
#define TPB    512
#define NBLK   (NTOK / TOKB) // 512

#define ZQ_OFF    0
#define CODES_OFF (NTOK * LC)                 // 4194304
#define LOSS_OFF  (CODES_OFF + NTOK * LLAY)   // 4456448

// device scratch (no allocation allowed)
__device__ float g_Mc[28 * 256];     // compact M[l][j] for j<l, pair p = l(l-1)/2+j
__device__ float g_v[LLAY * CDIM];
__device__ float g_c2[LLAY * KCODES];     // ||cbn_k||^2
__device__ float g_m2inv[LLAY * KCODES];  // -2 / max(||cb_k||, eps)
__device__ float g_partial[NBLK];

// ---------------- shared memory layout (floats) ----------------
#define S_AS    0                       // As[64][132]
#define S_ZQH   (S_AS + 64 * 132)       // zqh[64][132]
#define S_M     (S_ZQH + 64 * 132)      // m_s[7168]
#define S_V     (S_M + 7168)            // v_s[128]
#define S_ZR    (S_V + 128)             // zr[64][17]
#define S_ZN    (S_ZR + 64 * 17)        // zn[64][17]
#define S_INV   (S_ZN + 64 * 17)        // inv_s[64]
#define S_C2    (S_INV + 64)            // c2_s[1024]
#define S_M2I   (S_C2 + 1024)           // m2i_s[1024]
#define S_WINK  (S_M2I + 1024)          // wink[64] (int via bitcast)
#define S_RED   (S_WINK + 64)           // red[512]
#define S_CB    (S_RED + 512)           // cb_s[1024*17]  (aliased: zs/ws during A-GEMM)
#define S_TOTAL (S_CB + 1024 * 17)
#define SMEM_BYTES (S_TOTAL * 4)

// ---------------------------------------------------------------------------
__global__ void rvq_prep(const float* __restrict__ Wd, const float* __restrict__ bd,
                         const float* __restrict__ cb, const float* __restrict__ Wu,
                         const float* __restrict__ bu) {
    int tid = blockIdx.x * blockDim.x + threadIdx.x;
    if (tid < LLAY * KCODES) {
        // codebook norms
        const float* v = cb + (size_t)tid * CDIM;
        float ss = 0.f;
        #pragma unroll
        for (int c = 0; c < CDIM; c++) ss += v[c] * v[c];
        float nrm = sqrtf(ss);
        float inv = 1.f / fmaxf(nrm, 1e-12f);
        float c2 = 0.f;
        #pragma unroll
        for (int c = 0; c < CDIM; c++) { float x = v[c] * inv; c2 += x * x; }
        g_c2[tid] = c2;
        g_m2inv[tid] = -2.f * inv;
    } else if (tid < LLAY * KCODES + 28 * 256) {
        int i = tid - LLAY * KCODES;
        int p = i >> 8, r = i & 255;
        int c = r >> 4, e = r & 15;
        int l = 1;
        while (p >= l * (l + 1) / 2) l++;
        int j = p - l * (l - 1) / 2;
        const float* wdrow = Wd + ((size_t)l * CDIM + c) * DIM;
        const float* wucol = Wu + (size_t)j * DIM * CDIM + e;
        float acc = 0.f;
        for (int d = 0; d < DIM; d++) acc += wdrow[d] * wucol[(size_t)d * CDIM];
        g_Mc[p * 256 + c * CDIM + e] = acc;
    } else if (tid < LLAY * KCODES + 28 * 256 + LLAY * CDIM) {
        int i = tid - (LLAY * KCODES + 28 * 256);
        int l = i >> 4, c = i & 15;
        float acc = bd[l * CDIM + c];
        const float* wdrow = Wd + ((size_t)l * CDIM + c) * DIM;
        for (int j = 0; j < l; j++) {
            const float* burow = bu + (size_t)j * DIM;
            for (int d = 0; d < DIM; d++) acc -= wdrow[d] * burow[d];
        }
        g_v[i] = acc;
    }
}

// ---------------------------------------------------------------------------
__global__ __launch_bounds__(TPB, 1)
void rvq_main(const float* __restrict__ ze, const float* __restrict__ Wd,
              const float* __restrict__ cb, float* __restrict__ out) {
    extern __shared__ float sm[];
    float* As   = sm + S_AS;
    float* zqh  = sm + S_ZQH;
    float* m_s  = sm + S_M;
    float* v_s  = sm + S_V;
    float* zr   = sm + S_ZR;
    float* zn   = sm + S_ZN;
    float* invs = sm + S_INV;
    float* c2s  = sm + S_C2;
    float* m2is = sm + S_M2I;
    int*   wink = (int*)(sm + S_WINK);
    float* red  = sm + S_RED;
    float* cb_s = sm + S_CB;

    const int tid  = threadIdx.x;
    const int wid  = tid >> 5;
    const int lane = tid & 31;
    const int tok0 = blockIdx.x * TOKB;

    // load M and v
    for (int i = tid; i < 28 * 256; i += TPB) m_s[i] = g_Mc[i];
    if (tid < LLAY * CDIM) v_s[tid] = g_v[tid];

    // ================= A-GEMM: As[64][128] = ze_tile @ Wd_all^T ============
    {
        float* zs = cb_s;            // [32][68]
        float* ws = cb_s + 32 * 68;  // [32][132]
        float acc[4][4];
        #pragma unroll
        for (int i = 0; i < 4; i++)
            #pragma unroll
            for (int j = 0; j < 4; j++) acc[i][j] = 0.f;
        const int trow = wid * 4;   // 16 warps -> 64 tokens
        const int tcol = lane * 4;  // 32 lanes -> 128 cols
        for (int kc = 0; kc < DIM; kc += 32) {
            {
                int row = tid >> 3, q = tid & 7;
                float4 f = *(const float4*)(ze + (size_t)(tok0 + row) * DIM + kc + q * 4);
                zs[(q * 4 + 0) * 68 + row] = f.x;
                zs[(q * 4 + 1) * 68 + row] = f.y;
                zs[(q * 4 + 2) * 68 + row] = f.z;
                zs[(q * 4 + 3) * 68 + row] = f.w;
            }
            #pragma unroll
            for (int s = 0; s < 2; s++) {
                int idx = tid + s * TPB;
                int c = idx >> 3, q = idx & 7;
                float4 f = *(const float4*)(Wd + (size_t)c * DIM + kc + q * 4);
                ws[(q * 4 + 0) * 132 + c] = f.x;
                ws[(q * 4 + 1) * 132 + c] = f.y;
                ws[(q * 4 + 2) * 132 + c] = f.z;
                ws[(q * 4 + 3) * 132 + c] = f.w;
            }
            __syncthreads();
            #pragma unroll
            for (int k = 0; k < 32; k++) {
                float4 a = *(const float4*)(zs + k * 68 + trow);
                float4 b = *(const float4*)(ws + k * 132 + tcol);
                float av[4] = {a.x, a.y, a.z, a.w};
                float bv[4] = {b.x, b.y, b.z, b.w};
                #pragma unroll
                for (int i = 0; i < 4; i++)
                    #pragma unroll
                    for (int j = 0; j < 4; j++) acc[i][j] = fmaf(av[i], bv[j], acc[i][j]);
            }
            __syncthreads();
        }
        #pragma unroll
        for (int i = 0; i < 4; i++)
            #pragma unroll
            for (int j = 0; j < 4; j++) As[(trow + i) * 132 + tcol + j] = acc[i][j];
    }
    __syncthreads();

    // ================= sequential layers ===================================
    float lsum = 0.f;
    for (int l = 0; l < LLAY; l++) {
        // stage codebook (stride-17 padded) + scalars
        #pragma unroll
        for (int s = 0; s < 8; s++) {
            int idx = tid + s * TPB;          // 4096 float4
            int k = idx >> 2, q = idx & 3;
            float4 f = *(const float4*)(cb + ((size_t)l * KCODES + k) * CDIM + q * 4);
            cb_s[k * 17 + q * 4 + 0] = f.x;
            cb_s[k * 17 + q * 4 + 1] = f.y;
            cb_s[k * 17 + q * 4 + 2] = f.z;
            cb_s[k * 17 + q * 4 + 3] = f.w;
        }
        for (int i = tid; i < KCODES; i += TPB) {
            c2s[i]  = g_c2[l * KCODES + i];
            m2is[i] = g_m2inv[l * KCODES + i];
        }
        __syncthreads();

        // correction: z = A - sum_{j<l} M zq + v
        #pragma unroll
        for (int s = 0; s < 2; s++) {
            int pair = tid + s * TPB;
            int t = pair >> 4, c = pair & 15;
            float z = As[t * 132 + l * CDIM + c] + v_s[l * CDIM + c];
            for (int j = 0; j < l; j++) {
                int p = l * (l - 1) / 2 + j;
                const float* mrow = &m_s[p * 256 + c * CDIM];
                const float* q    = &zqh[t * 132 + j * CDIM];
                #pragma unroll
                for (int e = 0; e < CDIM; e++) z -= mrow[e] * q[e];
            }
            zr[t * 17 + c] = z;
        }
        __syncthreads();

        if (tid < TOKB) {
            float ss = 0.f;
            #pragma unroll
            for (int c = 0; c < CDIM; c++) { float x = zr[tid * 17 + c]; ss += x * x; }
            float nrm = sqrtf(ss);
            invs[tid] = 1.f / fmaxf(nrm, 1e-12f);
        }
        __syncthreads();
        #pragma unroll
        for (int s = 0; s < 2; s++) {
            int pair = tid + s * TPB;
            int t = pair >> 4, c = pair & 15;
            zn[t * 17 + c] = zr[t * 17 + c] * invs[t];
        }
        __syncthreads();

        // distances + argmin: warp handles 4 tokens, lane scans strided codes
        {
            float znr[4][CDIM];
            #pragma unroll
            for (int t4 = 0; t4 < 4; t4++)
                #pragma unroll
                for (int c = 0; c < CDIM; c++)
                    znr[t4][c] = zn[(wid * 4 + t4) * 17 + c];
            float bs[4]; int bk[4];
            #pragma unroll
            for (int t4 = 0; t4 < 4; t4++) { bs[t4] = 3.4e38f; bk[t4] = 0; }
            for (int j = 0; j < 32; j++) {
                int k = lane + j * 32;  // ascending k within lane => first-min tie-break
                float cv[CDIM];
                #pragma unroll
                for (int c = 0; c < CDIM; c++) cv[c] = cb_s[k * 17 + c];
                float c2k = c2s[k], mi = m2is[k];
                #pragma unroll
                for (int t4 = 0; t4 < 4; t4++) {
                    float dot = 0.f;
                    #pragma unroll
                    for (int c = 0; c < CDIM; c++) dot = fmaf(cv[c], znr[t4][c], dot);
                    float sc = fmaf(dot, mi, c2k);
                    if (sc < bs[t4]) { bs[t4] = sc; bk[t4] = k; }
                }
            }
            #pragma unroll
            for (int t4 = 0; t4 < 4; t4++) {
                float s = bs[t4]; int kk = bk[t4];
                #pragma unroll
                for (int off = 16; off > 0; off >>= 1) {
                    float os = __shfl_down_sync(0xffffffffu, s, off);
                    int   ok = __shfl_down_sync(0xffffffffu, kk, off);
                    if (os < s || (os == s && ok < kk)) { s = os; kk = ok; }
                }
                if (lane == 0) wink[wid * 4 + t4] = kk;
            }
        }
        __syncthreads();

        // gather + outputs + loss + history
        #pragma unroll
        for (int s = 0; s < 2; s++) {
            int pair = tid + s * TPB;
            int t = pair >> 4, c = pair & 15;
            int k = wink[t];
            float zq = cb_s[k * 17 + c];
            float z  = zr[t * 17 + c];
            zqh[t * 132 + l * CDIM + c] = zq;
            out[ZQ_OFF + (size_t)(tok0 + t) * LC + l * CDIM + c] = z + (zq - z);
            float d = z - zq;
            lsum += d * d;
            if (c == 0)
                out[CODES_OFF + (size_t)(tok0 + t) * LLAY + l] = (float)k;
        }
        __syncthreads();
    }

    // block loss reduction (deterministic: per-block partial)
    red[tid] = lsum;
    __syncthreads();
    for (int s = 256; s > 0; s >>= 1) {
        if (tid < s) red[tid] += red[tid + s];
        __syncthreads();
    }
    if (tid == 0) g_partial[blockIdx.x] = red[0];
}

// ---------------------------------------------------------------------------
__global__ void rvq_finalize(float* __restrict__ out) {
    __shared__ float red[TPB];
    int tid = threadIdx.x;
    red[tid] = g_partial[tid];
    __syncthreads();
    for (int s = 256; s > 0; s >>= 1) {
        if (tid < s) red[tid] += red[tid + s];
        __syncthreads();
    }
    if (tid == 0) {
        float total = red[0] / 524288.f;  // sum_l mean over B*T*CD
        out[LOSS_OFF + 0] = total;        // commitment_loss
        out[LOSS_OFF + 1] = total;        // codebook_loss (identical forward)
        out[LOSS_OFF + 2] = 0.f;          // entropy_loss
    }
}

// ---------------------------------------------------------------------------
extern "C" void kernel_launch(void* const* d_in, const int* in_sizes, int n_in,
                              void* d_out, int out_size) {
    const float* ze = (const float*)d_in[0];
    const float* Wd = (const float*)d_in[1];
    const float* bd = (const float*)d_in[2];
    const float* cb = (const float*)d_in[3];
    const float* Wu = (const float*)d_in[4];
    const float* bu = (const float*)d_in[5];
    float* out = (float*)d_out;

    cudaFuncSetAttribute(rvq_main, cudaFuncAttributeMaxDynamicSharedMemorySize, SMEM_BYTES);

    rvq_prep<<<61, 256>>>(Wd, bd, cb, Wu, bu);
    rvq_main<<<NBLK, TPB, SMEM_BYTES>>>(ze, Wd, cb, out);
    rvq_finalize<<<1, TPB>>>(out);
}

// round 6
// speedup vs baseline: 1.1676x; 1.1676x over previous
#include <cuda_runtime.h>
#include <cuda_bf16.h>
#include <cstdint>

// ---------------------------------------------------------------------------
// ResidualVQ restructured:
//   z_i^(l) = A_l(token) - sum_{j<l} M[l][j] @ zq_j + v_l
//   A = z_e @ Wd_all^T   (one GEMM, 32768x1024x128)
//   M[l][j] = Wd_l @ Wu_j (16x16),  v_l = bd_l - Wd_l @ sum_{j<l} bu_j
// Distances: score_k = ||cbn_k||^2 - 2 * zn . (cb_k * inv_k)   (argmin, fp32)
// This round: warp-parallel prep (was 350us serial-loop kernel) and packed
// fma.rn.f32x2 in the A-GEMM / distance / correction loops (2x fp32 FMA tput).
// ---------------------------------------------------------------------------

#define NTOK   32768
#define DIM    1024
#define KCODES 1024
#define CDIM   16
#define LLAY   8
#define LC     128           // L*CD
#define TOKB   64            // tokens per block
#define TPB    512
#define NBLK   (NTOK / TOKB) // 512

#define ZQ_OFF    0
#define CODES_OFF (NTOK * LC)                 // 4194304
#define LOSS_OFF  (CODES_OFF + NTOK * LLAY)   // 4456448

// device scratch (no allocation allowed)
__device__ float g_Mc[28 * 256];     // compact M[l][j] for j<l, pair p = l(l-1)/2+j
__device__ float g_v[LLAY * CDIM];
__device__ float g_c2[LLAY * KCODES];     // ||cbn_k||^2
__device__ float g_m2inv[LLAY * KCODES];  // -2 / max(||cb_k||, eps)
__device__ float g_partial[NBLK];

// ---------------- packed f32x2 helpers -------------------------------------
typedef unsigned long long u64;

__device__ __forceinline__ u64 ffma2(u64 a, u64 b, u64 c) {
    u64 d;
    asm("fma.rn.f32x2 %0, %1, %2, %3;" : "=l"(d) : "l"(a), "l"(b), "l"(c));
    return d;
}
__device__ __forceinline__ float f2lo(u64 v) { return __uint_as_float((unsigned)v); }
__device__ __forceinline__ float f2hi(u64 v) { return __uint_as_float((unsigned)(v >> 32)); }

// ---------------- shared memory layout (floats) ----------------
#define S_AS    0                       // As[64][132]
#define S_ZQH   (S_AS + 64 * 132)       // zqh[64][132]
#define S_M     (S_ZQH + 64 * 132)      // m_s[7168]
#define S_V     (S_M + 7168)            // v_s[128]
#define S_ZR    (S_V + 128)             // zr[64][18]  (even stride: f32x2-aligned)
#define S_ZN    (S_ZR + 64 * 18)        // zn[64][18]
#define S_INV   (S_ZN + 64 * 18)        // inv_s[64]
#define S_C2    (S_INV + 64)            // c2_s[1024]
#define S_M2I   (S_C2 + 1024)           // m2i_s[1024]
#define S_WINK  (S_M2I + 1024)          // wink[64] (int via bitcast)
#define S_RED   (S_WINK + 64)           // red[512]
#define S_CB    (S_RED + 512)           // cb2[8 planes][1024] float2 = 16384 floats
                                        //   (aliased: zs[32][68] + ws2[32][133] f2 in A-GEMM)
#define S_TOTAL (S_CB + 16384)
#define SMEM_BYTES (S_TOTAL * 4)

// ---------------------------------------------------------------------------
// prep 1: codebook norms, fully parallel (8192 independent outputs)
__global__ void rvq_norms(const float* __restrict__ cb) {
    int tid = blockIdx.x * blockDim.x + threadIdx.x;
    if (tid >= LLAY * KCODES) return;
    const float* v = cb + (size_t)tid * CDIM;
    float ss = 0.f;
    #pragma unroll
    for (int c = 0; c < CDIM; c++) ss += v[c] * v[c];
    float nrm = sqrtf(ss);
    float inv = 1.f / fmaxf(nrm, 1e-12f);
    float c2 = 0.f;
    #pragma unroll
    for (int c = 0; c < CDIM; c++) { float x = v[c] * inv; c2 += x * x; }
    g_c2[tid] = c2;
    g_m2inv[tid] = -2.f * inv;
}

// prep 2: M[l][j] (7168 scalars) and v_l (128 scalars), one WARP per scalar
// with a 32-way split of the 1024-length dot product + shuffle reduce.
__global__ void rvq_mv(const float* __restrict__ Wd, const float* __restrict__ bd,
                       const float* __restrict__ Wu, const float* __restrict__ bu) {
    int gw = (blockIdx.x * blockDim.x + threadIdx.x) >> 5;
    int lane = threadIdx.x & 31;
    if (gw < 28 * 256) {
        int p = gw >> 8, r = gw & 255;
        int c = r >> 4, e = r & 15;
        int l = 1;
        while (p >= l * (l + 1) / 2) l++;
        int j = p - l * (l - 1) / 2;
        const float* wdrow = Wd + ((size_t)l * CDIM + c) * DIM;
        const float* wucol = Wu + (size_t)j * DIM * CDIM + e;
        float acc = 0.f;
        #pragma unroll 8
        for (int d = lane; d < DIM; d += 32)
            acc = fmaf(wdrow[d], wucol[(size_t)d * CDIM], acc);
        #pragma unroll
        for (int off = 16; off > 0; off >>= 1)
            acc += __shfl_down_sync(0xffffffffu, acc, off);
        if (lane == 0) g_Mc[p * 256 + c * CDIM + e] = acc;
    } else if (gw < 28 * 256 + LLAY * CDIM) {
        int i = gw - 28 * 256;
        int l = i >> 4, c = i & 15;
        const float* wdrow = Wd + ((size_t)l * CDIM + c) * DIM;
        float acc = 0.f;
        for (int d = lane; d < DIM; d += 32) {
            float s = 0.f;
            for (int j = 0; j < l; j++) s += bu[(size_t)j * DIM + d];
            acc = fmaf(wdrow[d], s, acc);
        }
        #pragma unroll
        for (int off = 16; off > 0; off >>= 1)
            acc += __shfl_down_sync(0xffffffffu, acc, off);
        if (lane == 0) g_v[i] = bd[l * CDIM + c] - acc;
    }
}

// ---------------------------------------------------------------------------
__global__ __launch_bounds__(TPB, 1)
void rvq_main(const float* __restrict__ ze, const float* __restrict__ Wd,
              const float* __restrict__ cb, float* __restrict__ out) {
    extern __shared__ float sm[];
    float* As   = sm + S_AS;
    float* zqh  = sm + S_ZQH;
    float* m_s  = sm + S_M;
    float* v_s  = sm + S_V;
    float* zr   = sm + S_ZR;
    float* zn   = sm + S_ZN;
    float* invs = sm + S_INV;
    float* c2s  = sm + S_C2;
    float* m2is = sm + S_M2I;
    int*   wink = (int*)(sm + S_WINK);
    float* red  = sm + S_RED;
    float* cb2f = sm + S_CB;

    const int tid  = threadIdx.x;
    const int wid  = tid >> 5;
    const int lane = tid & 31;
    const int tok0 = blockIdx.x * TOKB;

    // load M and v
    for (int i = tid; i < 28 * 256; i += TPB) m_s[i] = g_Mc[i];
    if (tid < LLAY * CDIM) v_s[tid] = g_v[tid];

    // ================= A-GEMM: As[64][128] = ze_tile @ Wd_all^T ============
    // acc2[i][j]: packed pair of tokens (trow+2i, trow+2i+1) for col (lane+32j)
    {
        float* zs   = cb2f;               // [32][68]   (k-major, token cols)
        float* ws2f = cb2f + 32 * 68;     // [32][133] float2, pre-broadcast {w,w}
        u64 acc2[2][4];
        #pragma unroll
        for (int i = 0; i < 2; i++)
            #pragma unroll
            for (int j = 0; j < 4; j++) acc2[i][j] = 0ull;
        const int trow = wid * 4;   // 16 warps -> 64 tokens
        for (int kc = 0; kc < DIM; kc += 32) {
            {
                int row = tid >> 3, q = tid & 7;
                float4 f = *(const float4*)(ze + (size_t)(tok0 + row) * DIM + kc + q * 4);
                zs[(q * 4 + 0) * 68 + row] = f.x;
                zs[(q * 4 + 1) * 68 + row] = f.y;
                zs[(q * 4 + 2) * 68 + row] = f.z;
                zs[(q * 4 + 3) * 68 + row] = f.w;
            }
            #pragma unroll
            for (int s = 0; s < 2; s++) {
                int idx = tid + s * TPB;
                int c = idx >> 3, q = idx & 7;
                float4 f = *(const float4*)(Wd + (size_t)c * DIM + kc + q * 4);
                *(float2*)(ws2f + (q * 4 + 0) * 266 + 2 * c) = make_float2(f.x, f.x);
                *(float2*)(ws2f + (q * 4 + 1) * 266 + 2 * c) = make_float2(f.y, f.y);
                *(float2*)(ws2f + (q * 4 + 2) * 266 + 2 * c) = make_float2(f.z, f.z);
                *(float2*)(ws2f + (q * 4 + 3) * 266 + 2 * c) = make_float2(f.w, f.w);
            }
            __syncthreads();
            #pragma unroll
            for (int k = 0; k < 32; k++) {
                u64 a01 = *(const u64*)(zs + k * 68 + trow);
                u64 a23 = *(const u64*)(zs + k * 68 + trow + 2);
                #pragma unroll
                for (int j = 0; j < 4; j++) {
                    u64 w2 = *(const u64*)(ws2f + k * 266 + 2 * (lane + 32 * j));
                    acc2[0][j] = ffma2(a01, w2, acc2[0][j]);
                    acc2[1][j] = ffma2(a23, w2, acc2[1][j]);
                }
            }
            __syncthreads();
        }
        #pragma unroll
        for (int i = 0; i < 2; i++)
            #pragma unroll
            for (int j = 0; j < 4; j++) {
                int col = lane + 32 * j;
                As[(trow + 2 * i + 0) * 132 + col] = f2lo(acc2[i][j]);
                As[(trow + 2 * i + 1) * 132 + col] = f2hi(acc2[i][j]);
            }
    }
    __syncthreads();

    // ================= sequential layers ===================================
    float lsum = 0.f;
    for (int l = 0; l < LLAY; l++) {
        // stage codebook as 8 c-pair planes: cb2[cp][k] = {cb[k][2cp], cb[k][2cp+1]}
        // lane-consecutive k -> conflict-free STS/LDS.64 (global reads hit L2)
        #pragma unroll
        for (int s = 0; s < 8; s++) {
            int idx = tid + s * TPB;
            int k = idx & 1023, q = idx >> 10;     // q = 0..3
            float4 f = *(const float4*)(cb + ((size_t)l * KCODES + k) * CDIM + q * 4);
            *(float2*)(cb2f + (2 * q) * 2048 + 2 * k)     = make_float2(f.x, f.y);
            *(float2*)(cb2f + (2 * q + 1) * 2048 + 2 * k) = make_float2(f.z, f.w);
        }
        for (int i = tid; i < KCODES; i += TPB) {
            c2s[i]  = g_c2[l * KCODES + i];
            m2is[i] = g_m2inv[l * KCODES + i];
        }
        __syncthreads();

        // correction: z = A - sum_{j<l} M zq + v   (packed inner product)
        #pragma unroll
        for (int s = 0; s < 2; s++) {
            int pair = tid + s * TPB;
            int t = pair >> 4, c = pair & 15;
            float z = As[t * 132 + l * CDIM + c] + v_s[l * CDIM + c];
            for (int j = 0; j < l; j++) {
                int p = l * (l - 1) / 2 + j;
                const u64* mrow = (const u64*)(m_s + p * 256 + c * CDIM);
                const u64* q2   = (const u64*)(zqh + t * 132 + j * CDIM);
                u64 a2 = 0ull;
                #pragma unroll
                for (int e = 0; e < 8; e++) a2 = ffma2(mrow[e], q2[e], a2);
                z -= f2lo(a2) + f2hi(a2);
            }
            zr[t * 18 + c] = z;
        }
        __syncthreads();

        if (tid < TOKB) {
            float ss = 0.f;
            #pragma unroll
            for (int c = 0; c < CDIM; c++) { float x = zr[tid * 18 + c]; ss += x * x; }
            float nrm = sqrtf(ss);
            invs[tid] = 1.f / fmaxf(nrm, 1e-12f);
        }
        __syncthreads();
        #pragma unroll
        for (int s = 0; s < 2; s++) {
            int pair = tid + s * TPB;
            int t = pair >> 4, c = pair & 15;
            zn[t * 18 + c] = zr[t * 18 + c] * invs[t];
        }
        __syncthreads();

        // distances + argmin: warp handles 4 tokens, lane scans strided codes.
        // dot products accumulated as f32x2 pairs over the 8 c-pair planes.
        {
            u64 zn2[4][8];
            #pragma unroll
            for (int t4 = 0; t4 < 4; t4++)
                #pragma unroll
                for (int cp = 0; cp < 8; cp++)
                    zn2[t4][cp] = *(const u64*)(zn + (wid * 4 + t4) * 18 + 2 * cp);
            float bs[4]; int bk[4];
            #pragma unroll
            for (int t4 = 0; t4 < 4; t4++) { bs[t4] = 3.4e38f; bk[t4] = 0; }
            for (int j = 0; j < 32; j++) {
                int k = lane + j * 32;  // ascending k within lane => first-min tie-break
                const float* cbase = cb2f + 2 * k;
                u64 cv[8];
                #pragma unroll
                for (int cp = 0; cp < 8; cp++) cv[cp] = *(const u64*)(cbase + cp * 2048);
                float c2k = c2s[k], mi = m2is[k];
                #pragma unroll
                for (int t4 = 0; t4 < 4; t4++) {
                    u64 d2 = 0ull;
                    #pragma unroll
                    for (int cp = 0; cp < 8; cp++) d2 = ffma2(cv[cp], zn2[t4][cp], d2);
                    float dot = f2lo(d2) + f2hi(d2);
                    float sc = fmaf(dot, mi, c2k);
                    if (sc < bs[t4]) { bs[t4] = sc; bk[t4] = k; }
                }
            }
            #pragma unroll
            for (int t4 = 0; t4 < 4; t4++) {
                float s = bs[t4]; int kk = bk[t4];
                #pragma unroll
                for (int off = 16; off > 0; off >>= 1) {
                    float os = __shfl_down_sync(0xffffffffu, s, off);
                    int   ok = __shfl_down_sync(0xffffffffu, kk, off);
                    if (os < s || (os == s && ok < kk)) { s = os; kk = ok; }
                }
                if (lane == 0) wink[wid * 4 + t4] = kk;
            }
        }
        __syncthreads();

        // gather + outputs + loss + history
        #pragma unroll
        for (int s = 0; s < 2; s++) {
            int pair = tid + s * TPB;
            int t = pair >> 4, c = pair & 15;
            int k = wink[t];
            float zq = cb2f[(c >> 1) * 2048 + 2 * k + (c & 1)];
            float z  = zr[t * 18 + c];
            zqh[t * 132 + l * CDIM + c] = zq;
            out[ZQ_OFF + (size_t)(tok0 + t) * LC + l * CDIM + c] = z + (zq - z);
            float d = z - zq;
            lsum += d * d;
            if (c == 0)
                out[CODES_OFF + (size_t)(tok0 + t) * LLAY + l] = (float)k;
        }
        __syncthreads();
    }

    // block loss reduction (deterministic: per-block partial)
    red[tid] = lsum;
    __syncthreads();
    for (int s = 256; s > 0; s >>= 1) {
        if (tid < s) red[tid] += red[tid + s];
        __syncthreads();
    }
    if (tid == 0) g_partial[blockIdx.x] = red[0];
}

// ---------------------------------------------------------------------------
__global__ void rvq_finalize(float* __restrict__ out) {
    __shared__ float red[TPB];
    int tid = threadIdx.x;
    red[tid] = g_partial[tid];
    __syncthreads();
    for (int s = 256; s > 0; s >>= 1) {
        if (tid < s) red[tid] += red[tid + s];
        __syncthreads();
    }
    if (tid == 0) {
        float total = red[0] / 524288.f;  // sum_l mean over B*T*CD
        out[LOSS_OFF + 0] = total;        // commitment_loss
        out[LOSS_OFF + 1] = total;        // codebook_loss (identical forward)
        out[LOSS_OFF + 2] = 0.f;          // entropy_loss
    }
}

// ---------------------------------------------------------------------------
extern "C" void kernel_launch(void* const* d_in, const int* in_sizes, int n_in,
                              void* d_out, int out_size) {
    const float* ze = (const float*)d_in[0];
    const float* Wd = (const float*)d_in[1];
    const float* bd = (const float*)d_in[2];
    const float* cb = (const float*)d_in[3];
    const float* Wu = (const float*)d_in[4];
    const float* bu = (const float*)d_in[5];
    float* out = (float*)d_out;

    cudaFuncSetAttribute(rvq_main, cudaFuncAttributeMaxDynamicSharedMemorySize, SMEM_BYTES);

    rvq_norms<<<16, 512>>>(cb);
    rvq_mv<<<912, 256>>>(Wd, bd, Wu, bu);
    rvq_main<<<NBLK, TPB, SMEM_BYTES>>>(ze, Wd, cb, out);
    rvq_finalize<<<1, TPB>>>(out);
}

// round 14
// speedup vs baseline: 1.3921x; 1.1923x over previous
#include <cuda_runtime.h>
#include <cuda_bf16.h>
#include <cstdint>

// ---------------------------------------------------------------------------
// ResidualVQ restructured:
//   z_i^(l) = A_l(token) - sum_{j<l} P[l][j][code_j] + v_l
//   A = z_e @ Wd_all^T   (one GEMM, 32768x1024x128)
//   P[l][j][k] = (Wd_l @ Wu_j) @ cb_j[k]   (precomputed 28x1024x16 table)
// Distances: score_k = ||cbn_k||^2 - 2 * zn . (cb_k * inv_k)   (argmin, fp32)
// R7 design: corrections -> P-table gathers, occ 2, A-GEMM 8tok x 64col/warp.
// R10 fix: rvq_proj launched at 256 threads + __launch_bounds__ (1024-thread
// launch exceeded the 64K-reg/block file -> "too many resources").
// ---------------------------------------------------------------------------

#define NTOK   32768
#define DIM    1024
#define KCODES 1024
#define CDIM   16
#define LLAY   8
#define LC     128           // L*CD
#define TOKB   32            // tokens per block
#define TPB    256
#define NBLK   (NTOK / TOKB) // 1024

#define ZQ_OFF    0
#define CODES_OFF (NTOK * LC)                 // 4194304
#define LOSS_OFF  (CODES_OFF + NTOK * LLAY)   // 4456448

// device scratch (no allocation allowed)
__device__ float g_Mc[28 * 256];          // M[l][j] pairs, p = l(l-1)/2+j
__device__ float g_v[LLAY * CDIM];
__device__ float g_c2[LLAY * KCODES];     // ||cbn_k||^2
__device__ float g_m2inv[LLAY * KCODES];  // -2 / max(||cb_k||, eps)
__device__ float g_P[28 * KCODES * CDIM]; // P[p][k][c] = M_p @ cb_j[k]
__device__ float g_partial[NBLK];

// ---------------- packed f32x2 helpers -------------------------------------
typedef unsigned long long u64;

__device__ __forceinline__ u64 ffma2(u64 a, u64 b, u64 c) {
    u64 d;
    asm("fma.rn.f32x2 %0, %1, %2, %3;" : "=l"(d) : "l"(a), "l"(b), "l"(c));
    return d;
}
__device__ __forceinline__ float f2lo(u64 v) { return __uint_as_float((unsigned)v); }
__device__ __forceinline__ float f2hi(u64 v) { return __uint_as_float((unsigned)(v >> 32)); }

// ---------------- shared memory layout (floats) ----------------
#define S_AS    0                       // As[32][130]
#define S_V     (S_AS + 32 * 130)       // v_s[128]
#define S_ZR    (S_V + 128)             // zr[32][18]
#define S_ZN    (S_ZR + 32 * 18)        // zn[32][18]  (red[256] aliases, used after layers)
#define S_INV   (S_ZN + 32 * 18)        // inv_s[32]
#define S_C2M   (S_INV + 32)            // c2m2[1024] float2 {c2, m2inv}
#define S_KH    (S_C2M + 2048)          // khist[8][32] ints
#define S_CB    (S_KH + 256)            // cb2[8 planes][1024] float2 = 16384 floats
                                        //   A-GEMM aliases: zs[32][36] + ws2[32][256]
#define S_TOTAL (S_CB + 16384)
#define SMEM_BYTES (S_TOTAL * 4)

// ---------------------------------------------------------------------------
// prep 1: codebook norms
__global__ void rvq_norms(const float* __restrict__ cb) {
    int tid = blockIdx.x * blockDim.x + threadIdx.x;
    if (tid >= LLAY * KCODES) return;
    const float* v = cb + (size_t)tid * CDIM;
    float ss = 0.f;
    #pragma unroll
    for (int c = 0; c < CDIM; c++) ss += v[c] * v[c];
    float nrm = sqrtf(ss);
    float inv = 1.f / fmaxf(nrm, 1e-12f);
    float c2 = 0.f;
    #pragma unroll
    for (int c = 0; c < CDIM; c++) { float x = v[c] * inv; c2 += x * x; }
    g_c2[tid] = c2;
    g_m2inv[tid] = -2.f * inv;
}

// prep 2: M[l][j] (7168 scalars) and v_l (128 scalars), one WARP per scalar
__global__ void rvq_mv(const float* __restrict__ Wd, const float* __restrict__ bd,
                       const float* __restrict__ Wu, const float* __restrict__ bu) {
    int gw = (blockIdx.x * blockDim.x + threadIdx.x) >> 5;
    int lane = threadIdx.x & 31;
    if (gw < 28 * 256) {
        int p = gw >> 8, r = gw & 255;
        int c = r >> 4, e = r & 15;
        int l = 1;
        while (p >= l * (l + 1) / 2) l++;
        int j = p - l * (l - 1) / 2;
        const float* wdrow = Wd + ((size_t)l * CDIM + c) * DIM;
        const float* wucol = Wu + (size_t)j * DIM * CDIM + e;
        float acc = 0.f;
        #pragma unroll 8
        for (int d = lane; d < DIM; d += 32)
            acc = fmaf(wdrow[d], wucol[(size_t)d * CDIM], acc);
        #pragma unroll
        for (int off = 16; off > 0; off >>= 1)
            acc += __shfl_down_sync(0xffffffffu, acc, off);
        if (lane == 0) g_Mc[p * 256 + c * CDIM + e] = acc;
    } else if (gw < 28 * 256 + LLAY * CDIM) {
        int i = gw - 28 * 256;
        int l = i >> 4, c = i & 15;
        const float* wdrow = Wd + ((size_t)l * CDIM + c) * DIM;
        float acc = 0.f;
        for (int d = lane; d < DIM; d += 32) {
            float s = 0.f;
            for (int j = 0; j < l; j++) s += bu[(size_t)j * DIM + d];
            acc = fmaf(wdrow[d], s, acc);
        }
        #pragma unroll
        for (int off = 16; off > 0; off >>= 1)
            acc += __shfl_down_sync(0xffffffffu, acc, off);
        if (lane == 0) g_v[i] = bd[l * CDIM + c] - acc;
    }
}

// prep 3: P[p][k][c] = sum_e M_p[c][e] * cb[j][k][e].  One block per pair p.
// 256 threads (4 k per thread) -- 1024-thread launch blew the reg file.
__global__ __launch_bounds__(256)
void rvq_proj(const float* __restrict__ cb) {
    __shared__ float msh[256];
    int p = blockIdx.x;
    int l = 1;
    while (p >= l * (l + 1) / 2) l++;
    int j = p - l * (l - 1) / 2;
    msh[threadIdx.x] = g_Mc[p * 256 + threadIdx.x];
    __syncthreads();
    for (int k = threadIdx.x; k < KCODES; k += 256) {
        float cv[CDIM];
        const float4* src = (const float4*)(cb + ((size_t)j * KCODES + k) * CDIM);
        #pragma unroll
        for (int q = 0; q < 4; q++) {
            float4 f = src[q];
            cv[q * 4 + 0] = f.x; cv[q * 4 + 1] = f.y;
            cv[q * 4 + 2] = f.z; cv[q * 4 + 3] = f.w;
        }
        float* dst = g_P + ((size_t)p * KCODES + k) * CDIM;
        #pragma unroll
        for (int c = 0; c < CDIM; c++) {
            float acc = 0.f;
            #pragma unroll
            for (int e = 0; e < CDIM; e++) acc = fmaf(msh[c * CDIM + e], cv[e], acc);
            dst[c] = acc;
        }
    }
}

// ---------------------------------------------------------------------------
__global__ __launch_bounds__(TPB, 2)
void rvq_main(const float* __restrict__ ze, const float* __restrict__ Wd,
              const float* __restrict__ cb, float* __restrict__ out) {
    extern __shared__ float sm[];
    float* As   = sm + S_AS;
    float* v_s  = sm + S_V;
    float* zr   = sm + S_ZR;
    float* zn   = sm + S_ZN;
    float* invs = sm + S_INV;
    float* c2m  = sm + S_C2M;   // float2 pairs
    int*   kh   = (int*)(sm + S_KH);
    float* cb2f = sm + S_CB;

    const int tid  = threadIdx.x;
    const int wid  = tid >> 5;
    const int lane = tid & 31;
    const int tok0 = blockIdx.x * TOKB;

    if (tid < LLAY * CDIM) v_s[tid] = g_v[tid];

    // ================= A-GEMM: As[32][128] = ze_tile @ Wd_all^T ============
    // warp tile: 8 tokens x 64 cols.  tg = wid>>1 (token group), cg = wid&1.
    // acc2[tp][ch] = packed tokens (tg*8+2tp, +1), col = cg*64 + ch*32 + lane.
    {
        float* zs   = cb2f;               // [32 k][36]  zs[k*36 + t]
        float* ws2f = cb2f + 32 * 36;     // [32 k][256] dup {w,w} per col
        u64 acc2[4][2];
        #pragma unroll
        for (int i = 0; i < 4; i++) { acc2[i][0] = 0ull; acc2[i][1] = 0ull; }
        const int tg = wid >> 1, cg = wid & 1;
        const int tbase = tg * 8;
        const int cbase = cg * 64 + lane;
        for (int kc = 0; kc < DIM; kc += 32) {
            {   // stage ze: 32 tokens x 32 k
                int row = tid >> 3, q = tid & 7;
                float4 f = *(const float4*)(ze + (size_t)(tok0 + row) * DIM + kc + q * 4);
                zs[(q * 4 + 0) * 36 + row] = f.x;
                zs[(q * 4 + 1) * 36 + row] = f.y;
                zs[(q * 4 + 2) * 36 + row] = f.z;
                zs[(q * 4 + 3) * 36 + row] = f.w;
            }
            #pragma unroll
            for (int s = 0; s < 4; s++) {  // stage Wd dup'd: 128 cols x 32 k
                int idx = tid + s * TPB;
                int c = idx & 127, q = idx >> 7;
                float4 f = *(const float4*)(Wd + (size_t)c * DIM + kc + q * 4);
                *(float2*)(ws2f + (q * 4 + 0) * 256 + 2 * c) = make_float2(f.x, f.x);
                *(float2*)(ws2f + (q * 4 + 1) * 256 + 2 * c) = make_float2(f.y, f.y);
                *(float2*)(ws2f + (q * 4 + 2) * 256 + 2 * c) = make_float2(f.z, f.z);
                *(float2*)(ws2f + (q * 4 + 3) * 256 + 2 * c) = make_float2(f.w, f.w);
            }
            __syncthreads();
            #pragma unroll
            for (int k = 0; k < 32; k++) {
                u64 w0 = *(const u64*)(ws2f + k * 256 + 2 * cbase);
                u64 w1 = *(const u64*)(ws2f + k * 256 + 2 * (cbase + 32));
                #pragma unroll
                for (int tp = 0; tp < 4; tp++) {
                    u64 a = *(const u64*)(zs + k * 36 + tbase + 2 * tp);  // broadcast
                    acc2[tp][0] = ffma2(a, w0, acc2[tp][0]);
                    acc2[tp][1] = ffma2(a, w1, acc2[tp][1]);
                }
            }
            __syncthreads();
        }
        #pragma unroll
        for (int tp = 0; tp < 4; tp++)
            #pragma unroll
            for (int ch = 0; ch < 2; ch++) {
                int col = cbase + ch * 32;
                As[(tbase + 2 * tp + 0) * 130 + col] = f2lo(acc2[tp][ch]);
                As[(tbase + 2 * tp + 1) * 130 + col] = f2hi(acc2[tp][ch]);
            }
    }
    __syncthreads();

    // ================= sequential layers ===================================
    float lsum = 0.f;
    for (int l = 0; l < LLAY; l++) {
        // stage codebook as 8 c-pair planes + packed {c2, m2inv}
        #pragma unroll
        for (int s = 0; s < 16; s++) {
            int idx = tid + s * TPB;
            int k = idx & 1023, q = idx >> 10;
            float4 f = *(const float4*)(cb + ((size_t)l * KCODES + k) * CDIM + q * 4);
            *(float2*)(cb2f + (2 * q) * 2048 + 2 * k)     = make_float2(f.x, f.y);
            *(float2*)(cb2f + (2 * q + 1) * 2048 + 2 * k) = make_float2(f.z, f.w);
        }
        #pragma unroll
        for (int s = 0; s < 4; s++) {
            int k = tid + s * TPB;
            *(float2*)(c2m + 2 * k) = make_float2(g_c2[l * KCODES + k],
                                                  g_m2inv[l * KCODES + k]);
        }
        __syncthreads();

        // correction via P-table gathers: z = A + v - sum_{j<l} P[p][code_j]
        #pragma unroll
        for (int s = 0; s < 2; s++) {
            int pair = tid + s * TPB;
            int t = pair >> 4, c = pair & 15;
            float z = As[t * 130 + l * CDIM + c] + v_s[l * CDIM + c];
            int pbase = l * (l - 1) / 2;
            for (int j = 0; j < l; j++) {
                int code = kh[j * TOKB + t];
                z -= g_P[(((size_t)(pbase + j)) * KCODES + code) * CDIM + c];
            }
            zr[t * 18 + c] = z;
        }
        __syncthreads();

        if (tid < TOKB) {
            float ss = 0.f;
            #pragma unroll
            for (int c = 0; c < CDIM; c++) { float x = zr[tid * 18 + c]; ss += x * x; }
            invs[tid] = 1.f / fmaxf(sqrtf(ss), 1e-12f);
        }
        __syncthreads();
        #pragma unroll
        for (int s = 0; s < 2; s++) {
            int pair = tid + s * TPB;
            int t = pair >> 4, c = pair & 15;
            zn[t * 18 + c] = zr[t * 18 + c] * invs[t];
        }
        __syncthreads();

        // distances + argmin: warp handles 4 tokens, lane scans strided codes
        {
            u64 zn2[4][8];
            #pragma unroll
            for (int t4 = 0; t4 < 4; t4++)
                #pragma unroll
                for (int cp = 0; cp < 8; cp++)
                    zn2[t4][cp] = *(const u64*)(zn + (wid * 4 + t4) * 18 + 2 * cp);
            float bs[4]; int bk[4];
            #pragma unroll
            for (int t4 = 0; t4 < 4; t4++) { bs[t4] = 3.4e38f; bk[t4] = 0; }
            for (int j = 0; j < 32; j++) {
                int k = lane + j * 32;  // ascending k within lane => first-min tie-break
                const float* cbase2 = cb2f + 2 * k;
                u64 cv[8];
                #pragma unroll
                for (int cp = 0; cp < 8; cp++) cv[cp] = *(const u64*)(cbase2 + cp * 2048);
                float2 cm = *(const float2*)(c2m + 2 * k);
                #pragma unroll
                for (int t4 = 0; t4 < 4; t4++) {
                    u64 d2 = 0ull;
                    #pragma unroll
                    for (int cp = 0; cp < 8; cp++) d2 = ffma2(cv[cp], zn2[t4][cp], d2);
                    float dot = f2lo(d2) + f2hi(d2);
                    float sc = fmaf(dot, cm.y, cm.x);
                    if (sc < bs[t4]) { bs[t4] = sc; bk[t4] = k; }
                }
            }
            #pragma unroll
            for (int t4 = 0; t4 < 4; t4++) {
                float s = bs[t4]; int kk = bk[t4];
                #pragma unroll
                for (int off = 16; off > 0; off >>= 1) {
                    float os = __shfl_down_sync(0xffffffffu, s, off);
                    int   ok = __shfl_down_sync(0xffffffffu, kk, off);
                    if (os < s || (os == s && ok < kk)) { s = os; kk = ok; }
                }
                if (lane == 0) kh[l * TOKB + wid * 4 + t4] = kk;
            }
        }
        __syncthreads();

        // gather + outputs + loss
        #pragma unroll
        for (int s = 0; s < 2; s++) {
            int pair = tid + s * TPB;
            int t = pair >> 4, c = pair & 15;
            int k = kh[l * TOKB + t];
            float zq = cb2f[(c >> 1) * 2048 + 2 * k + (c & 1)];
            float z  = zr[t * 18 + c];
            out[ZQ_OFF + (size_t)(tok0 + t) * LC + l * CDIM + c] = z + (zq - z);
            float d = z - zq;
            lsum += d * d;
            if (c == 0)
                out[CODES_OFF + (size_t)(tok0 + t) * LLAY + l] = (float)k;
        }
        __syncthreads();
    }

    // block loss reduction (red aliases zn region, dead by now)
    float* red = zn;
    red[tid] = lsum;
    __syncthreads();
    for (int s = 128; s > 0; s >>= 1) {
        if (tid < s) red[tid] += red[tid + s];
        __syncthreads();
    }
    if (tid == 0) g_partial[blockIdx.x] = red[0];
}

// ---------------------------------------------------------------------------
__global__ void rvq_finalize(float* __restrict__ out) {
    __shared__ float red[512];
    int tid = threadIdx.x;
    red[tid] = g_partial[tid] + g_partial[tid + 512];
    __syncthreads();
    for (int s = 256; s > 0; s >>= 1) {
        if (tid < s) red[tid] += red[tid + s];
        __syncthreads();
    }
    if (tid == 0) {
        float total = red[0] / 524288.f;  // sum_l mean over B*T*CD
        out[LOSS_OFF + 0] = total;        // commitment_loss
        out[LOSS_OFF + 1] = total;        // codebook_loss (identical forward)
        out[LOSS_OFF + 2] = 0.f;          // entropy_loss
    }
}

// ---------------------------------------------------------------------------
extern "C" void kernel_launch(void* const* d_in, const int* in_sizes, int n_in,
                              void* d_out, int out_size) {
    const float* ze = (const float*)d_in[0];
    const float* Wd = (const float*)d_in[1];
    const float* bd = (const float*)d_in[2];
    const float* cb = (const float*)d_in[3];
    const float* Wu = (const float*)d_in[4];
    const float* bu = (const float*)d_in[5];
    float* out = (float*)d_out;

    cudaFuncSetAttribute(rvq_main, cudaFuncAttributeMaxDynamicSharedMemorySize, SMEM_BYTES);

    rvq_norms<<<16, 512>>>(cb);
    rvq_mv<<<912, 256>>>(Wd, bd, Wu, bu);
    rvq_proj<<<28, 256>>>(cb);
    rvq_main<<<NBLK, TPB, SMEM_BYTES>>>(ze, Wd, cb, out);
    rvq_finalize<<<1, 512>>>(out);
}